// round 10
// baseline (speedup 1.0000x reference)
#include <cuda_runtime.h>
#include <math.h>

// ---------------------------------------------------------------------------
// GCN 2-layer, CSR-gather formulation (no float atomics):
//   k_zero/k_count: in-degree histogram
//   k_scan: ONE single-block kernel -> offsets, cursors, dinv
//   k_fill: CSR {row, norm} grouped by destination
//   k_gemm1: h1 = x@W1
//   k_gather1: agg1[c] = dinv^2 h1[c] + sum nrm*h1[r]   (warp/node, x4 unroll)
//   k_gemm2: h2 = relu(agg1+b1)@W2
//   k_gather2: out[c] = gather(h2) + b2, fused log_softmax epilogue
// edge_index arrives as int32 (JAX x64 disabled downcasts int64).
// ---------------------------------------------------------------------------

#define NN 50000
#define EE 800000
#define F1 128
#define F2 64
#define F3 40
#define SCAN_T 512

// Scratch (device globals: no allocation allowed)
__device__ int   g_cnt[NN];            // in-degree (real edges)
__device__ float g_dinv[NN];           // 1/sqrt(deg+1)
__device__ int   g_off[NN + 1];        // CSR offsets
__device__ int   g_cur[NN];            // fill cursors
__device__ __align__(8)  int2  g_csr[EE];         // {row, norm-as-int}
__device__ __align__(16) float g_h1[NN * F2];     // x@W1
__device__ __align__(16) float g_agg1[NN * F2];   // layer-1 aggregation
__device__ __align__(16) float g_h2[NN * F3];     // relu(agg1+b1)@W2

// ---------------------------------------------------------------------------
__global__ void k_zero(int N) {
    int i = blockIdx.x * blockDim.x + threadIdx.x;
    if (i < N) g_cnt[i] = 0;
}

__global__ void k_count(const int* __restrict__ ei, int E) {
    int e = blockIdx.x * blockDim.x + threadIdx.x;
    if (e < E) atomicAdd(&g_cnt[ei[E + e]], 1);
}

// single-block scan: offsets (exclusive), cursors, dinv — one launch
__global__ void k_scan(int N, int E) {
    __shared__ int part[SCAN_T];
    const int t = threadIdx.x;
    const int chunk = (N + SCAN_T - 1) / SCAN_T;
    const int lo = t * chunk;
    const int hi = (lo + chunk < N) ? lo + chunk : N;

    int sum = 0;
    for (int i = lo; i < hi; i++) sum += g_cnt[i];
    part[t] = sum;
    __syncthreads();
#pragma unroll
    for (int st = 1; st < SCAN_T; st <<= 1) {
        int add = (t >= st) ? part[t - st] : 0;
        __syncthreads();
        part[t] += add;
        __syncthreads();
    }
    int base = part[t] - sum;  // exclusive prefix for this chunk
    for (int i = lo; i < hi; i++) {
        int c = g_cnt[i];
        g_off[i] = base;
        g_cur[i] = base;
        g_dinv[i] = rsqrtf((float)c + 1.0f);
        base += c;
    }
    if (t == 0) g_off[N] = E;
}

// fill CSR: {row, norm} per edge, grouped by destination col
__global__ void k_fill(const int* __restrict__ ei, int E) {
    int e = blockIdx.x * blockDim.x + threadIdx.x;
    if (e < E) {
        int r = ei[e];
        int c = ei[E + e];
        int p = atomicAdd(&g_cur[c], 1);
        float nrm = g_dinv[r] * g_dinv[c];
        g_csr[p] = make_int2(r, __float_as_int(nrm));
    }
}

// ---------------------------------------------------------------------------
// GEMM1: h1[N,64] = x[N,128] @ W1[128,64]
__global__ void k_gemm1(const float* __restrict__ x, const float* __restrict__ W,
                        int N) {
    __shared__ float Ws[32][64];
    __shared__ float Xs[32][68];
    const int bro = blockIdx.x * 64;
    const int t = threadIdx.x;
    const int tr = t >> 4;
    const int tc = t & 15;

    float acc[4][4];
#pragma unroll
    for (int i = 0; i < 4; i++)
#pragma unroll
        for (int j = 0; j < 4; j++) acc[i][j] = 0.0f;

    for (int k0 = 0; k0 < F1; k0 += 32) {
        {
            const float4* Wg = (const float4*)(W + k0 * 64);
            float4* Wsm = (float4*)&Ws[0][0];
            Wsm[t] = Wg[t];
            Wsm[t + 256] = Wg[t + 256];
        }
#pragma unroll
        for (int it = 0; it < 2; it++) {
            int idx = t + it * 256;
            int row = idx >> 3;
            int kq = idx & 7;
            int grow = bro + row;
            float4 v = make_float4(0.f, 0.f, 0.f, 0.f);
            if (grow < N)
                v = *(const float4*)(x + (size_t)grow * F1 + k0 + kq * 4);
            Xs[kq * 4 + 0][row] = v.x;
            Xs[kq * 4 + 1][row] = v.y;
            Xs[kq * 4 + 2][row] = v.z;
            Xs[kq * 4 + 3][row] = v.w;
        }
        __syncthreads();
#pragma unroll
        for (int k = 0; k < 32; k++) {
            float4 a = *(const float4*)&Xs[k][tr * 4];
            float4 b = *(const float4*)&Ws[k][tc * 4];
            float av[4] = {a.x, a.y, a.z, a.w};
            float bv[4] = {b.x, b.y, b.z, b.w};
#pragma unroll
            for (int i = 0; i < 4; i++)
#pragma unroll
                for (int j = 0; j < 4; j++) acc[i][j] = fmaf(av[i], bv[j], acc[i][j]);
        }
        __syncthreads();
    }
#pragma unroll
    for (int i = 0; i < 4; i++) {
        int row = bro + tr * 4 + i;
        if (row < N) {
            float4 v = make_float4(acc[i][0], acc[i][1], acc[i][2], acc[i][3]);
            *(float4*)&g_h1[(size_t)row * F2 + tc * 4] = v;
        }
    }
}

// ---------------------------------------------------------------------------
// gather layer 1: warp per node, lane owns 2 feature cols (64 = 32*2)
// edge loop unrolled x4 for MLP (independent row-gathers in flight)
__global__ void k_gather1(int N) {
    int warp = (blockIdx.x * blockDim.x + threadIdx.x) >> 5;
    int lane = threadIdx.x & 31;
    if (warp >= N) return;
    const int c = warp;
    const float d = g_dinv[c];
    const float d2 = d * d;

    float2 self = *(const float2*)&g_h1[(size_t)c * F2 + lane * 2];
    float ax = d2 * self.x, ay = d2 * self.y;

    int j = g_off[c];
    const int end = g_off[c + 1];
    for (; j + 4 <= end; j += 4) {
        int2 e0 = __ldg(&g_csr[j + 0]);
        int2 e1 = __ldg(&g_csr[j + 1]);
        int2 e2 = __ldg(&g_csr[j + 2]);
        int2 e3 = __ldg(&g_csr[j + 3]);
        float2 v0 = *(const float2*)&g_h1[(size_t)e0.x * F2 + lane * 2];
        float2 v1 = *(const float2*)&g_h1[(size_t)e1.x * F2 + lane * 2];
        float2 v2 = *(const float2*)&g_h1[(size_t)e2.x * F2 + lane * 2];
        float2 v3 = *(const float2*)&g_h1[(size_t)e3.x * F2 + lane * 2];
        ax = fmaf(__int_as_float(e0.y), v0.x, ax);
        ay = fmaf(__int_as_float(e0.y), v0.y, ay);
        ax = fmaf(__int_as_float(e1.y), v1.x, ax);
        ay = fmaf(__int_as_float(e1.y), v1.y, ay);
        ax = fmaf(__int_as_float(e2.y), v2.x, ax);
        ay = fmaf(__int_as_float(e2.y), v2.y, ay);
        ax = fmaf(__int_as_float(e3.y), v3.x, ax);
        ay = fmaf(__int_as_float(e3.y), v3.y, ay);
    }
    for (; j < end; j++) {
        int2 en = __ldg(&g_csr[j]);
        float nrm = __int_as_float(en.y);
        float2 v = *(const float2*)&g_h1[(size_t)en.x * F2 + lane * 2];
        ax = fmaf(nrm, v.x, ax);
        ay = fmaf(nrm, v.y, ay);
    }
    *(float2*)&g_agg1[(size_t)c * F2 + lane * 2] = make_float2(ax, ay);
}

// ---------------------------------------------------------------------------
// GEMM2: h2[N,40] = relu(agg1 + b1)[N,64] @ W2[64,40]
__global__ void k_gemm2(const float* __restrict__ W2, const float* __restrict__ b1,
                        int N) {
    __shared__ float Ws[64][40];
    __shared__ float As[64][68];
    __shared__ float bs[64];
    const int bro = blockIdx.x * 64;
    const int t = threadIdx.x;

    for (int idx = t; idx < 64 * 40; idx += 256) ((float*)Ws)[idx] = W2[idx];
    if (t < 64) bs[t] = b1[t];
    __syncthreads();

#pragma unroll
    for (int it = 0; it < 4; it++) {
        int idx = t + it * 256;
        int row = idx >> 4;
        int kq = idx & 15;
        int grow = bro + row;
        float4 v = make_float4(0.f, 0.f, 0.f, 0.f);
        if (grow < N)
            v = *(const float4*)&g_agg1[(size_t)grow * F2 + kq * 4];
        As[kq * 4 + 0][row] = fmaxf(v.x + bs[kq * 4 + 0], 0.0f);
        As[kq * 4 + 1][row] = fmaxf(v.y + bs[kq * 4 + 1], 0.0f);
        As[kq * 4 + 2][row] = fmaxf(v.z + bs[kq * 4 + 2], 0.0f);
        As[kq * 4 + 3][row] = fmaxf(v.w + bs[kq * 4 + 3], 0.0f);
    }
    __syncthreads();

    const int tr = t >> 3;
    const int tc = t & 7;
    float acc[2][5];
#pragma unroll
    for (int i = 0; i < 2; i++)
#pragma unroll
        for (int j = 0; j < 5; j++) acc[i][j] = 0.0f;

#pragma unroll
    for (int k = 0; k < 64; k++) {
        float2 a = *(const float2*)&As[k][tr * 2];
        float w0 = Ws[k][tc * 5 + 0];
        float w1 = Ws[k][tc * 5 + 1];
        float w2 = Ws[k][tc * 5 + 2];
        float w3 = Ws[k][tc * 5 + 3];
        float w4 = Ws[k][tc * 5 + 4];
        acc[0][0] = fmaf(a.x, w0, acc[0][0]);
        acc[0][1] = fmaf(a.x, w1, acc[0][1]);
        acc[0][2] = fmaf(a.x, w2, acc[0][2]);
        acc[0][3] = fmaf(a.x, w3, acc[0][3]);
        acc[0][4] = fmaf(a.x, w4, acc[0][4]);
        acc[1][0] = fmaf(a.y, w0, acc[1][0]);
        acc[1][1] = fmaf(a.y, w1, acc[1][1]);
        acc[1][2] = fmaf(a.y, w2, acc[1][2]);
        acc[1][3] = fmaf(a.y, w3, acc[1][3]);
        acc[1][4] = fmaf(a.y, w4, acc[1][4]);
    }
#pragma unroll
    for (int i = 0; i < 2; i++) {
        int row = bro + tr * 2 + i;
        if (row < N) {
#pragma unroll
            for (int j = 0; j < 5; j++)
                g_h2[(size_t)row * F3 + tc * 5 + j] = acc[i][j];
        }
    }
}

// ---------------------------------------------------------------------------
// gather layer 2 + fused bias + log_softmax epilogue
// warp per node; lanes 0..19 own 2 feature cols; all 32 lanes stay alive
// for the warp reductions (inactive lanes contribute -INF / 0).
__global__ void k_gather2(float* __restrict__ out, const float* __restrict__ b2,
                          int N) {
    int warp = (blockIdx.x * blockDim.x + threadIdx.x) >> 5;
    int lane = threadIdx.x & 31;
    if (warp >= N) return;
    const int c = warp;
    const bool act = (lane < 20);
    const int col = act ? lane : 0;       // clamped float2 column index
    const float2* __restrict__ H = (const float2*)g_h2;   // row = 20 float2

    float d = g_dinv[c];
    float d2 = d * d;
    float2 s = H[(size_t)c * 20 + col];
    float ax = d2 * s.x, ay = d2 * s.y;

    int j = g_off[c];
    const int end = g_off[c + 1];
    for (; j + 4 <= end; j += 4) {
        int2 e0 = __ldg(&g_csr[j + 0]);
        int2 e1 = __ldg(&g_csr[j + 1]);
        int2 e2 = __ldg(&g_csr[j + 2]);
        int2 e3 = __ldg(&g_csr[j + 3]);
        float2 v0 = H[(size_t)e0.x * 20 + col];
        float2 v1 = H[(size_t)e1.x * 20 + col];
        float2 v2 = H[(size_t)e2.x * 20 + col];
        float2 v3 = H[(size_t)e3.x * 20 + col];
        ax = fmaf(__int_as_float(e0.y), v0.x, ax);
        ay = fmaf(__int_as_float(e0.y), v0.y, ay);
        ax = fmaf(__int_as_float(e1.y), v1.x, ax);
        ay = fmaf(__int_as_float(e1.y), v1.y, ay);
        ax = fmaf(__int_as_float(e2.y), v2.x, ax);
        ay = fmaf(__int_as_float(e2.y), v2.y, ay);
        ax = fmaf(__int_as_float(e3.y), v3.x, ax);
        ay = fmaf(__int_as_float(e3.y), v3.y, ay);
    }
    for (; j < end; j++) {
        int2 en = __ldg(&g_csr[j]);
        float nrm = __int_as_float(en.y);
        float2 v = H[(size_t)en.x * 20 + col];
        ax = fmaf(nrm, v.x, ax);
        ay = fmaf(nrm, v.y, ay);
    }

    // + b2, then log_softmax across the 40 values held by lanes 0..19
    if (act) {
        float2 b = ((const float2*)b2)[lane];
        ax += b.x; ay += b.y;
    } else {
        ax = -INFINITY; ay = -INFINITY;
    }
    float m = fmaxf(ax, ay);
#pragma unroll
    for (int st = 16; st > 0; st >>= 1)
        m = fmaxf(m, __shfl_xor_sync(0xFFFFFFFFu, m, st));

    float es = act ? (expf(ax - m) + expf(ay - m)) : 0.0f;
#pragma unroll
    for (int st = 16; st > 0; st >>= 1)
        es += __shfl_xor_sync(0xFFFFFFFFu, es, st);

    float l = m + logf(es);
    if (act)
        ((float2*)out)[(size_t)c * 20 + lane] = make_float2(ax - l, ay - l);
}

// ---------------------------------------------------------------------------
extern "C" void kernel_launch(void* const* d_in, const int* in_sizes, int n_in,
                              void* d_out, int out_size) {
    const float* x   = (const float*)d_in[0];
    const int* ei    = (const int*)d_in[1];   // int32 (JAX x64 disabled)
    const float* W1  = (const float*)d_in[2];
    const float* b1  = (const float*)d_in[3];
    const float* W2  = (const float*)d_in[4];
    const float* b2  = (const float*)d_in[5];
    float* out       = (float*)d_out;

    const int N = in_sizes[0] / F1;
    const int E = in_sizes[1] / 2;

    // CSR build (4 launches)
    k_zero<<<(N + 255) / 256, 256>>>(N);
    k_count<<<(E + 255) / 256, 256>>>(ei, E);
    k_scan<<<1, SCAN_T>>>(N, E);
    k_fill<<<(E + 255) / 256, 256>>>(ei, E);

    // layer 1
    k_gemm1<<<(N + 63) / 64, 256>>>(x, W1, N);
    k_gather1<<<(N + 7) / 8, 256>>>(N);

    // layer 2 (+fused epilogue)
    k_gemm2<<<(N + 63) / 64, 256>>>(W2, b1, N);
    k_gather2<<<(N + 7) / 8, 256>>>(out, b2, N);
}

// round 11
// speedup vs baseline: 1.8254x; 1.8254x over previous
#include <cuda_runtime.h>
#include <math.h>

// ---------------------------------------------------------------------------
// GCN 2-layer, CSR-gather with factored symmetric norm:
//   hs = (x@W) scaled by dinv[row] in GEMM epilogue
//   agg[c] = dinv[c] * ( hs[c] + sum_{e: col=c} hs[row_e] )   — plain sum!
//   CSR stores ONLY row indices (4 B/edge).
// Prep: 4-kernel scan pipeline (proven; single-block scan was a 95us trap).
// edge_index arrives as int32 (JAX x64 disabled downcasts int64).
// ---------------------------------------------------------------------------

#define NN 50000
#define EE 800000
#define F1 128
#define F2 64
#define F3 40
#define SCAN_BS 512
#define MAX_NB 256

// Scratch (device globals: no allocation allowed)
__device__ int   g_cnt[NN];            // in-degree (real edges)
__device__ float g_dinv[NN];           // 1/sqrt(deg+1)
__device__ int   g_off[NN + 1];        // CSR offsets
__device__ int   g_cur[NN];            // fill cursors
__device__ int   g_bsum[MAX_NB];       // scan partials
__device__ int   g_bpre[MAX_NB];
__device__ int   g_csri[EE];           // CSR row indices only
__device__ __align__(16) float g_h1[NN * F2];     // dinv-scaled x@W1
__device__ __align__(16) float g_agg1[NN * F2];   // layer-1 aggregation
__device__ __align__(16) float g_h2[NN * F3];     // dinv-scaled relu(agg1+b1)@W2

// ---------------------------------------------------------------------------
__global__ void k_zero(int N) {
    int i = blockIdx.x * blockDim.x + threadIdx.x;
    if (i < N) g_cnt[i] = 0;
}

__global__ void k_count(const int* __restrict__ ei, int E) {
    int e = blockIdx.x * blockDim.x + threadIdx.x;
    if (e < E) atomicAdd(&g_cnt[ei[E + e]], 1);
}

__global__ void k_dinv(int N) {
    int i = blockIdx.x * blockDim.x + threadIdx.x;
    if (i < N) g_dinv[i] = rsqrtf((float)g_cnt[i] + 1.0f);
}

// scan step A: per-block sums of g_cnt
__global__ void k_scanA(int N) {
    __shared__ int s[SCAN_BS];
    int i = blockIdx.x * SCAN_BS + threadIdx.x;
    s[threadIdx.x] = (i < N) ? g_cnt[i] : 0;
    __syncthreads();
    for (int st = SCAN_BS / 2; st > 0; st >>= 1) {
        if (threadIdx.x < st) s[threadIdx.x] += s[threadIdx.x + st];
        __syncthreads();
    }
    if (threadIdx.x == 0 && blockIdx.x < MAX_NB) g_bsum[blockIdx.x] = s[0];
}

// scan step B: serial exclusive scan of block sums (tiny)
__global__ void k_scanB(int NB, int N, int E) {
    if (threadIdx.x == 0) {
        int run = 0;
        int nb = (NB < MAX_NB) ? NB : MAX_NB;
        for (int b = 0; b < nb; b++) { g_bpre[b] = run; run += g_bsum[b]; }
        g_off[N] = E;
    }
}

// scan step C: intra-block exclusive scan + block prefix -> offsets & cursors
__global__ void k_scanC(int N) {
    __shared__ int s[SCAN_BS];
    int i = blockIdx.x * SCAN_BS + threadIdx.x;
    int v = (i < N) ? g_cnt[i] : 0;
    s[threadIdx.x] = v;
    __syncthreads();
#pragma unroll
    for (int st = 1; st < SCAN_BS; st <<= 1) {
        int add = (threadIdx.x >= st) ? s[threadIdx.x - st] : 0;
        __syncthreads();
        s[threadIdx.x] += add;
        __syncthreads();
    }
    if (i < N) {
        int excl = g_bpre[blockIdx.x] + s[threadIdx.x] - v;
        g_off[i] = excl;
        g_cur[i] = excl;
    }
}

// fill CSR: row index per edge, grouped by destination col (no norm needed)
__global__ void k_fill(const int* __restrict__ ei, int E) {
    int e = blockIdx.x * blockDim.x + threadIdx.x;
    if (e < E) {
        int r = ei[e];
        int c = ei[E + e];
        int p = atomicAdd(&g_cur[c], 1);
        g_csri[p] = r;
    }
}

// ---------------------------------------------------------------------------
// GEMM1: h1s[N,64] = dinv[row] * (x[N,128] @ W1[128,64])
__global__ void k_gemm1(const float* __restrict__ x, const float* __restrict__ W,
                        int N) {
    __shared__ float Ws[32][64];
    __shared__ float Xs[32][68];
    const int bro = blockIdx.x * 64;
    const int t = threadIdx.x;
    const int tr = t >> 4;
    const int tc = t & 15;

    float acc[4][4];
#pragma unroll
    for (int i = 0; i < 4; i++)
#pragma unroll
        for (int j = 0; j < 4; j++) acc[i][j] = 0.0f;

    for (int k0 = 0; k0 < F1; k0 += 32) {
        {
            const float4* Wg = (const float4*)(W + k0 * 64);
            float4* Wsm = (float4*)&Ws[0][0];
            Wsm[t] = Wg[t];
            Wsm[t + 256] = Wg[t + 256];
        }
#pragma unroll
        for (int it = 0; it < 2; it++) {
            int idx = t + it * 256;
            int row = idx >> 3;
            int kq = idx & 7;
            int grow = bro + row;
            float4 v = make_float4(0.f, 0.f, 0.f, 0.f);
            if (grow < N)
                v = *(const float4*)(x + (size_t)grow * F1 + k0 + kq * 4);
            Xs[kq * 4 + 0][row] = v.x;
            Xs[kq * 4 + 1][row] = v.y;
            Xs[kq * 4 + 2][row] = v.z;
            Xs[kq * 4 + 3][row] = v.w;
        }
        __syncthreads();
#pragma unroll
        for (int k = 0; k < 32; k++) {
            float4 a = *(const float4*)&Xs[k][tr * 4];
            float4 b = *(const float4*)&Ws[k][tc * 4];
            float av[4] = {a.x, a.y, a.z, a.w};
            float bv[4] = {b.x, b.y, b.z, b.w};
#pragma unroll
            for (int i = 0; i < 4; i++)
#pragma unroll
                for (int j = 0; j < 4; j++) acc[i][j] = fmaf(av[i], bv[j], acc[i][j]);
        }
        __syncthreads();
    }
#pragma unroll
    for (int i = 0; i < 4; i++) {
        int row = bro + tr * 4 + i;
        if (row < N) {
            float dr = g_dinv[row];
            float4 v = make_float4(dr * acc[i][0], dr * acc[i][1],
                                   dr * acc[i][2], dr * acc[i][3]);
            *(float4*)&g_h1[(size_t)row * F2 + tc * 4] = v;
        }
    }
}

// ---------------------------------------------------------------------------
// gather layer 1: warp per node, lane owns 2 feature cols (64 = 32*2)
// plain sum of pre-scaled rows; final multiply by dinv[c]; x4 unroll for MLP
__global__ void k_gather1(int N) {
    int warp = (blockIdx.x * blockDim.x + threadIdx.x) >> 5;
    int lane = threadIdx.x & 31;
    if (warp >= N) return;
    const int c = warp;

    float2 self = *(const float2*)&g_h1[(size_t)c * F2 + lane * 2];
    float ax = self.x, ay = self.y;

    int j = g_off[c];
    const int end = g_off[c + 1];
    for (; j + 4 <= end; j += 4) {
        int r0 = __ldg(&g_csri[j + 0]);
        int r1 = __ldg(&g_csri[j + 1]);
        int r2 = __ldg(&g_csri[j + 2]);
        int r3 = __ldg(&g_csri[j + 3]);
        float2 v0 = *(const float2*)&g_h1[(size_t)r0 * F2 + lane * 2];
        float2 v1 = *(const float2*)&g_h1[(size_t)r1 * F2 + lane * 2];
        float2 v2 = *(const float2*)&g_h1[(size_t)r2 * F2 + lane * 2];
        float2 v3 = *(const float2*)&g_h1[(size_t)r3 * F2 + lane * 2];
        ax += v0.x + v1.x + v2.x + v3.x;
        ay += v0.y + v1.y + v2.y + v3.y;
    }
    for (; j < end; j++) {
        int r = __ldg(&g_csri[j]);
        float2 v = *(const float2*)&g_h1[(size_t)r * F2 + lane * 2];
        ax += v.x;
        ay += v.y;
    }
    float d = g_dinv[c];
    *(float2*)&g_agg1[(size_t)c * F2 + lane * 2] = make_float2(d * ax, d * ay);
}

// ---------------------------------------------------------------------------
// GEMM2: h2s[N,40] = dinv[row] * (relu(agg1 + b1)[N,64] @ W2[64,40])
__global__ void k_gemm2(const float* __restrict__ W2, const float* __restrict__ b1,
                        int N) {
    __shared__ float Ws[64][40];
    __shared__ float As[64][68];
    __shared__ float bs[64];
    const int bro = blockIdx.x * 64;
    const int t = threadIdx.x;

    for (int idx = t; idx < 64 * 40; idx += 256) ((float*)Ws)[idx] = W2[idx];
    if (t < 64) bs[t] = b1[t];
    __syncthreads();

#pragma unroll
    for (int it = 0; it < 4; it++) {
        int idx = t + it * 256;
        int row = idx >> 4;
        int kq = idx & 15;
        int grow = bro + row;
        float4 v = make_float4(0.f, 0.f, 0.f, 0.f);
        if (grow < N)
            v = *(const float4*)&g_agg1[(size_t)grow * F2 + kq * 4];
        As[kq * 4 + 0][row] = fmaxf(v.x + bs[kq * 4 + 0], 0.0f);
        As[kq * 4 + 1][row] = fmaxf(v.y + bs[kq * 4 + 1], 0.0f);
        As[kq * 4 + 2][row] = fmaxf(v.z + bs[kq * 4 + 2], 0.0f);
        As[kq * 4 + 3][row] = fmaxf(v.w + bs[kq * 4 + 3], 0.0f);
    }
    __syncthreads();

    const int tr = t >> 3;
    const int tc = t & 7;
    float acc[2][5];
#pragma unroll
    for (int i = 0; i < 2; i++)
#pragma unroll
        for (int j = 0; j < 5; j++) acc[i][j] = 0.0f;

#pragma unroll
    for (int k = 0; k < 64; k++) {
        float2 a = *(const float2*)&As[k][tr * 2];
        float w0 = Ws[k][tc * 5 + 0];
        float w1 = Ws[k][tc * 5 + 1];
        float w2 = Ws[k][tc * 5 + 2];
        float w3 = Ws[k][tc * 5 + 3];
        float w4 = Ws[k][tc * 5 + 4];
        acc[0][0] = fmaf(a.x, w0, acc[0][0]);
        acc[0][1] = fmaf(a.x, w1, acc[0][1]);
        acc[0][2] = fmaf(a.x, w2, acc[0][2]);
        acc[0][3] = fmaf(a.x, w3, acc[0][3]);
        acc[0][4] = fmaf(a.x, w4, acc[0][4]);
        acc[1][0] = fmaf(a.y, w0, acc[1][0]);
        acc[1][1] = fmaf(a.y, w1, acc[1][1]);
        acc[1][2] = fmaf(a.y, w2, acc[1][2]);
        acc[1][3] = fmaf(a.y, w3, acc[1][3]);
        acc[1][4] = fmaf(a.y, w4, acc[1][4]);
    }
#pragma unroll
    for (int i = 0; i < 2; i++) {
        int row = bro + tr * 2 + i;
        if (row < N) {
            float dr = g_dinv[row];
#pragma unroll
            for (int j = 0; j < 5; j++)
                g_h2[(size_t)row * F3 + tc * 5 + j] = dr * acc[i][j];
        }
    }
}

// ---------------------------------------------------------------------------
// gather layer 2 + final scale + bias + fused log_softmax epilogue
// warp per node; lanes 0..19 own 2 feature cols; all 32 lanes stay alive
// for the warp reductions (inactive lanes contribute -INF / 0).
__global__ void k_gather2(float* __restrict__ out, const float* __restrict__ b2,
                          int N) {
    int warp = (blockIdx.x * blockDim.x + threadIdx.x) >> 5;
    int lane = threadIdx.x & 31;
    if (warp >= N) return;
    const int c = warp;
    const bool act = (lane < 20);
    const int col = act ? lane : 0;       // clamped float2 column index
    const float2* __restrict__ H = (const float2*)g_h2;   // row = 20 float2

    float2 s = H[(size_t)c * 20 + col];
    float ax = s.x, ay = s.y;

    int j = g_off[c];
    const int end = g_off[c + 1];
    for (; j + 4 <= end; j += 4) {
        int r0 = __ldg(&g_csri[j + 0]);
        int r1 = __ldg(&g_csri[j + 1]);
        int r2 = __ldg(&g_csri[j + 2]);
        int r3 = __ldg(&g_csri[j + 3]);
        float2 v0 = H[(size_t)r0 * 20 + col];
        float2 v1 = H[(size_t)r1 * 20 + col];
        float2 v2 = H[(size_t)r2 * 20 + col];
        float2 v3 = H[(size_t)r3 * 20 + col];
        ax += v0.x + v1.x + v2.x + v3.x;
        ay += v0.y + v1.y + v2.y + v3.y;
    }
    for (; j < end; j++) {
        int r = __ldg(&g_csri[j]);
        float2 v = H[(size_t)r * 20 + col];
        ax += v.x;
        ay += v.y;
    }

    // final dinv[c] scale, + b2, then log_softmax across the 40 values
    float d = g_dinv[c];
    if (act) {
        float2 b = ((const float2*)b2)[lane];
        ax = d * ax + b.x;
        ay = d * ay + b.y;
    } else {
        ax = -INFINITY; ay = -INFINITY;
    }
    float m = fmaxf(ax, ay);
#pragma unroll
    for (int st = 16; st > 0; st >>= 1)
        m = fmaxf(m, __shfl_xor_sync(0xFFFFFFFFu, m, st));

    float es = act ? (expf(ax - m) + expf(ay - m)) : 0.0f;
#pragma unroll
    for (int st = 16; st > 0; st >>= 1)
        es += __shfl_xor_sync(0xFFFFFFFFu, es, st);

    float l = m + logf(es);
    if (act)
        ((float2*)out)[(size_t)c * 20 + lane] = make_float2(ax - l, ay - l);
}

// ---------------------------------------------------------------------------
extern "C" void kernel_launch(void* const* d_in, const int* in_sizes, int n_in,
                              void* d_out, int out_size) {
    const float* x   = (const float*)d_in[0];
    const int* ei    = (const int*)d_in[1];   // int32 (JAX x64 disabled)
    const float* W1  = (const float*)d_in[2];
    const float* b1  = (const float*)d_in[3];
    const float* W2  = (const float*)d_in[4];
    const float* b2  = (const float*)d_in[5];
    float* out       = (float*)d_out;

    const int N = in_sizes[0] / F1;
    const int E = in_sizes[1] / 2;
    const int NB = (N + SCAN_BS - 1) / SCAN_BS;

    // CSR build (multi-block scan pipeline — do NOT single-block this)
    k_zero<<<(N + 255) / 256, 256>>>(N);
    k_count<<<(E + 255) / 256, 256>>>(ei, E);
    k_dinv<<<(N + 255) / 256, 256>>>(N);
    k_scanA<<<NB, SCAN_BS>>>(N);
    k_scanB<<<1, 32>>>(NB, N, E);
    k_scanC<<<NB, SCAN_BS>>>(N);
    k_fill<<<(E + 255) / 256, 256>>>(ei, E);

    // layer 1
    k_gemm1<<<(N + 63) / 64, 256>>>(x, W1, N);
    k_gather1<<<(N + 7) / 8, 256>>>(N);

    // layer 2 (+fused epilogue)
    k_gemm2<<<(N + 63) / 64, 256>>>(W2, b1, N);
    k_gather2<<<(N + 7) / 8, 256>>>(out, b2, N);
}

// round 13
// speedup vs baseline: 1.9486x; 1.0675x over previous
#include <cuda_runtime.h>
#include <math.h>

// ---------------------------------------------------------------------------
// GCN 2-layer, CSR-gather with factored symmetric norm:
//   hs = (x@W) scaled by dinv[row] in GEMM epilogue
//   agg[c] = dinv[c] * ( hs[c] + sum_{e: col=c} hs[row_e] )   — plain sum
//   CSR stores ONLY row indices (4 B/edge).
// Prep chain = 4 launches: count -> scanA -> scanC(fused dinv+prefix+clean)
//   -> fill.  g_cnt is zero at entry (module-load init + scanC self-clean).
// edge_index arrives as int32 (JAX x64 disabled downcasts int64).
// ---------------------------------------------------------------------------

#define NN 50000
#define EE 800000
#define F1 128
#define F2 64
#define F3 40
#define SCAN_BS 512
#define MAX_NB 128     // ceil(50000/512)=98 <= 128

// Scratch (device globals: no allocation allowed; zero-initialized at load)
__device__ int   g_cnt[NN];            // in-degree; ALWAYS zero at entry
__device__ float g_dinv[NN];           // 1/sqrt(deg+1)
__device__ int   g_off[NN + 1];        // CSR offsets
__device__ int   g_cur[NN];            // fill cursors
__device__ int   g_bsum[MAX_NB];       // scan partials
__device__ int   g_csri[EE];           // CSR row indices only
__device__ __align__(16) float g_h1[NN * F2];     // dinv-scaled x@W1
__device__ __align__(16) float g_agg1[NN * F2];   // layer-1 aggregation
__device__ __align__(16) float g_h2[NN * F3];     // dinv-scaled relu(agg1+b1)@W2

// ---------------------------------------------------------------------------
__global__ void k_count(const int* __restrict__ ei, int E) {
    int e = blockIdx.x * blockDim.x + threadIdx.x;
    if (e < E) atomicAdd(&g_cnt[ei[E + e]], 1);
}

// scan step A: per-block sums of g_cnt
__global__ void k_scanA(int N) {
    __shared__ int s[SCAN_BS];
    int i = blockIdx.x * SCAN_BS + threadIdx.x;
    s[threadIdx.x] = (i < N) ? g_cnt[i] : 0;
    __syncthreads();
    for (int st = SCAN_BS / 2; st > 0; st >>= 1) {
        if (threadIdx.x < st) s[threadIdx.x] += s[threadIdx.x + st];
        __syncthreads();
    }
    if (threadIdx.x == 0 && blockIdx.x < MAX_NB) g_bsum[blockIdx.x] = s[0];
}

// scan step C (fused): intra-block scan + own block-prefix from g_bsum +
// offsets + cursors + dinv + self-clean of g_cnt for the next replay.
__global__ void k_scanC(int N, int E) {
    __shared__ int s[SCAN_BS];
    __shared__ int bs_sh[MAX_NB];
    __shared__ int bpre_sh;
    const int t = threadIdx.x;
    const int i = blockIdx.x * SCAN_BS + t;

    int v = (i < N) ? g_cnt[i] : 0;
    if (i < N) g_cnt[i] = 0;              // self-clean for next graph replay
    s[t] = v;
    if (t < MAX_NB) bs_sh[t] = (t < blockIdx.x) ? g_bsum[t] : 0;
    __syncthreads();
#pragma unroll
    for (int st = 1; st < SCAN_BS; st <<= 1) {
        int add = (t >= st) ? s[t - st] : 0;
        __syncthreads();
        s[t] += add;
        __syncthreads();
    }
    if (t == 0) {
        int run = 0;
        for (int b = 0; b < MAX_NB; b++) run += bs_sh[b];
        bpre_sh = run;
    }
    __syncthreads();
    if (i < N) {
        int excl = bpre_sh + s[t] - v;    // exclusive prefix
        g_off[i] = excl;
        g_cur[i] = excl;
        g_dinv[i] = rsqrtf((float)v + 1.0f);
    }
    if (i == 0) g_off[N] = E;
}

// fill CSR: row index per edge, grouped by destination col
__global__ void k_fill(const int* __restrict__ ei, int E) {
    int e = blockIdx.x * blockDim.x + threadIdx.x;
    if (e < E) {
        int r = ei[e];
        int c = ei[E + e];
        int p = atomicAdd(&g_cur[c], 1);
        g_csri[p] = r;
    }
}

// ---------------------------------------------------------------------------
// GEMM1: h1s[N,64] = dinv[row] * (x[N,128] @ W1[128,64])
__global__ void k_gemm1(const float* __restrict__ x, const float* __restrict__ W,
                        int N) {
    __shared__ float Ws[32][64];
    __shared__ float Xs[32][68];
    const int bro = blockIdx.x * 64;
    const int t = threadIdx.x;
    const int tr = t >> 4;
    const int tc = t & 15;

    float acc[4][4];
#pragma unroll
    for (int i = 0; i < 4; i++)
#pragma unroll
        for (int j = 0; j < 4; j++) acc[i][j] = 0.0f;

    for (int k0 = 0; k0 < F1; k0 += 32) {
        {
            const float4* Wg = (const float4*)(W + k0 * 64);
            float4* Wsm = (float4*)&Ws[0][0];
            Wsm[t] = Wg[t];
            Wsm[t + 256] = Wg[t + 256];
        }
#pragma unroll
        for (int it = 0; it < 2; it++) {
            int idx = t + it * 256;
            int row = idx >> 3;
            int kq = idx & 7;
            int grow = bro + row;
            float4 v = make_float4(0.f, 0.f, 0.f, 0.f);
            if (grow < N)
                v = *(const float4*)(x + (size_t)grow * F1 + k0 + kq * 4);
            Xs[kq * 4 + 0][row] = v.x;
            Xs[kq * 4 + 1][row] = v.y;
            Xs[kq * 4 + 2][row] = v.z;
            Xs[kq * 4 + 3][row] = v.w;
        }
        __syncthreads();
#pragma unroll
        for (int k = 0; k < 32; k++) {
            float4 a = *(const float4*)&Xs[k][tr * 4];
            float4 b = *(const float4*)&Ws[k][tc * 4];
            float av[4] = {a.x, a.y, a.z, a.w};
            float bv[4] = {b.x, b.y, b.z, b.w};
#pragma unroll
            for (int i = 0; i < 4; i++)
#pragma unroll
                for (int j = 0; j < 4; j++) acc[i][j] = fmaf(av[i], bv[j], acc[i][j]);
        }
        __syncthreads();
    }
#pragma unroll
    for (int i = 0; i < 4; i++) {
        int row = bro + tr * 4 + i;
        if (row < N) {
            float dr = g_dinv[row];
            float4 v = make_float4(dr * acc[i][0], dr * acc[i][1],
                                   dr * acc[i][2], dr * acc[i][3]);
            *(float4*)&g_h1[(size_t)row * F2 + tc * 4] = v;
        }
    }
}

// ---------------------------------------------------------------------------
// gather layer 1: warp per node, lane owns 2 feature cols (64 = 32*2)
// plain sum of pre-scaled rows; final multiply by dinv[c]; x4 unroll for MLP
__global__ void k_gather1(int N) {
    int warp = (blockIdx.x * blockDim.x + threadIdx.x) >> 5;
    int lane = threadIdx.x & 31;
    if (warp >= N) return;
    const int c = warp;

    float2 self = *(const float2*)&g_h1[(size_t)c * F2 + lane * 2];
    float ax = self.x, ay = self.y;

    int j = g_off[c];
    const int end = g_off[c + 1];
    for (; j + 4 <= end; j += 4) {
        int r0 = __ldg(&g_csri[j + 0]);
        int r1 = __ldg(&g_csri[j + 1]);
        int r2 = __ldg(&g_csri[j + 2]);
        int r3 = __ldg(&g_csri[j + 3]);
        float2 v0 = *(const float2*)&g_h1[(size_t)r0 * F2 + lane * 2];
        float2 v1 = *(const float2*)&g_h1[(size_t)r1 * F2 + lane * 2];
        float2 v2 = *(const float2*)&g_h1[(size_t)r2 * F2 + lane * 2];
        float2 v3 = *(const float2*)&g_h1[(size_t)r3 * F2 + lane * 2];
        ax += v0.x + v1.x + v2.x + v3.x;
        ay += v0.y + v1.y + v2.y + v3.y;
    }
    for (; j < end; j++) {
        int r = __ldg(&g_csri[j]);
        float2 v = *(const float2*)&g_h1[(size_t)r * F2 + lane * 2];
        ax += v.x;
        ay += v.y;
    }
    float d = g_dinv[c];
    *(float2*)&g_agg1[(size_t)c * F2 + lane * 2] = make_float2(d * ax, d * ay);
}

// ---------------------------------------------------------------------------
// GEMM2: h2s[N,40] = dinv[row] * (relu(agg1 + b1)[N,64] @ W2[64,40])
__global__ void k_gemm2(const float* __restrict__ W2, const float* __restrict__ b1,
                        int N) {
    __shared__ float Ws[64][40];
    __shared__ float As[64][68];
    __shared__ float bs[64];
    const int bro = blockIdx.x * 64;
    const int t = threadIdx.x;

    for (int idx = t; idx < 64 * 40; idx += 256) ((float*)Ws)[idx] = W2[idx];
    if (t < 64) bs[t] = b1[t];
    __syncthreads();

#pragma unroll
    for (int it = 0; it < 4; it++) {
        int idx = t + it * 256;
        int row = idx >> 4;
        int kq = idx & 15;
        int grow = bro + row;
        float4 v = make_float4(0.f, 0.f, 0.f, 0.f);
        if (grow < N)
            v = *(const float4*)&g_agg1[(size_t)grow * F2 + kq * 4];
        As[kq * 4 + 0][row] = fmaxf(v.x + bs[kq * 4 + 0], 0.0f);
        As[kq * 4 + 1][row] = fmaxf(v.y + bs[kq * 4 + 1], 0.0f);
        As[kq * 4 + 2][row] = fmaxf(v.z + bs[kq * 4 + 2], 0.0f);
        As[kq * 4 + 3][row] = fmaxf(v.w + bs[kq * 4 + 3], 0.0f);
    }
    __syncthreads();

    const int tr = t >> 3;
    const int tc = t & 7;
    float acc[2][5];
#pragma unroll
    for (int i = 0; i < 2; i++)
#pragma unroll
        for (int j = 0; j < 5; j++) acc[i][j] = 0.0f;

#pragma unroll
    for (int k = 0; k < 64; k++) {
        float2 a = *(const float2*)&As[k][tr * 2];
        float w0 = Ws[k][tc * 5 + 0];
        float w1 = Ws[k][tc * 5 + 1];
        float w2 = Ws[k][tc * 5 + 2];
        float w3 = Ws[k][tc * 5 + 3];
        float w4 = Ws[k][tc * 5 + 4];
        acc[0][0] = fmaf(a.x, w0, acc[0][0]);
        acc[0][1] = fmaf(a.x, w1, acc[0][1]);
        acc[0][2] = fmaf(a.x, w2, acc[0][2]);
        acc[0][3] = fmaf(a.x, w3, acc[0][3]);
        acc[0][4] = fmaf(a.x, w4, acc[0][4]);
        acc[1][0] = fmaf(a.y, w0, acc[1][0]);
        acc[1][1] = fmaf(a.y, w1, acc[1][1]);
        acc[1][2] = fmaf(a.y, w2, acc[1][2]);
        acc[1][3] = fmaf(a.y, w3, acc[1][3]);
        acc[1][4] = fmaf(a.y, w4, acc[1][4]);
    }
#pragma unroll
    for (int i = 0; i < 2; i++) {
        int row = bro + tr * 2 + i;
        if (row < N) {
            float dr = g_dinv[row];
#pragma unroll
            for (int j = 0; j < 5; j++)
                g_h2[(size_t)row * F3 + tc * 5 + j] = dr * acc[i][j];
        }
    }
}

// ---------------------------------------------------------------------------
// gather layer 2 + final scale + bias + fused log_softmax epilogue
// warp per node; lanes 0..19 own 2 feature cols; all 32 lanes stay alive
// for the warp reductions (inactive lanes contribute -INF / 0).
__global__ void k_gather2(float* __restrict__ out, const float* __restrict__ b2,
                          int N) {
    int warp = (blockIdx.x * blockDim.x + threadIdx.x) >> 5;
    int lane = threadIdx.x & 31;
    if (warp >= N) return;
    const int c = warp;
    const bool act = (lane < 20);
    const int col = act ? lane : 0;       // clamped float2 column index
    const float2* __restrict__ H = (const float2*)g_h2;   // row = 20 float2

    float2 s = H[(size_t)c * 20 + col];
    float ax = s.x, ay = s.y;

    int j = g_off[c];
    const int end = g_off[c + 1];
    for (; j + 4 <= end; j += 4) {
        int r0 = __ldg(&g_csri[j + 0]);
        int r1 = __ldg(&g_csri[j + 1]);
        int r2 = __ldg(&g_csri[j + 2]);
        int r3 = __ldg(&g_csri[j + 3]);
        float2 v0 = H[(size_t)r0 * 20 + col];
        float2 v1 = H[(size_t)r1 * 20 + col];
        float2 v2 = H[(size_t)r2 * 20 + col];
        float2 v3 = H[(size_t)r3 * 20 + col];
        ax += v0.x + v1.x + v2.x + v3.x;
        ay += v0.y + v1.y + v2.y + v3.y;
    }
    for (; j < end; j++) {
        int r = __ldg(&g_csri[j]);
        float2 v = H[(size_t)r * 20 + col];
        ax += v.x;
        ay += v.y;
    }

    // final dinv[c] scale, + b2, then log_softmax across the 40 values
    float d = g_dinv[c];
    if (act) {
        float2 b = ((const float2*)b2)[lane];
        ax = d * ax + b.x;
        ay = d * ay + b.y;
    } else {
        ax = -INFINITY; ay = -INFINITY;
    }
    float m = fmaxf(ax, ay);
#pragma unroll
    for (int st = 16; st > 0; st >>= 1)
        m = fmaxf(m, __shfl_xor_sync(0xFFFFFFFFu, m, st));

    float es = act ? (expf(ax - m) + expf(ay - m)) : 0.0f;
#pragma unroll
    for (int st = 16; st > 0; st >>= 1)
        es += __shfl_xor_sync(0xFFFFFFFFu, es, st);

    float l = m + logf(es);
    if (act)
        ((float2*)out)[(size_t)c * 20 + lane] = make_float2(ax - l, ay - l);
}

// ---------------------------------------------------------------------------
extern "C" void kernel_launch(void* const* d_in, const int* in_sizes, int n_in,
                              void* d_out, int out_size) {
    const float* x   = (const float*)d_in[0];
    const int* ei    = (const int*)d_in[1];   // int32 (JAX x64 disabled)
    const float* W1  = (const float*)d_in[2];
    const float* b1  = (const float*)d_in[3];
    const float* W2  = (const float*)d_in[4];
    const float* b2  = (const float*)d_in[5];
    float* out       = (float*)d_out;

    const int N = in_sizes[0] / F1;
    const int E = in_sizes[1] / 2;
    const int NB = (N + SCAN_BS - 1) / SCAN_BS;

    // CSR build — 4 launches (g_cnt is zero at entry: load-init + self-clean)
    k_count<<<(E + 255) / 256, 256>>>(ei, E);
    k_scanA<<<NB, SCAN_BS>>>(N);
    k_scanC<<<NB, SCAN_BS>>>(N, E);
    k_fill<<<(E + 255) / 256, 256>>>(ei, E);

    // layer 1
    k_gemm1<<<(N + 63) / 64, 256>>>(x, W1, N);
    k_gather1<<<(N + 7) / 8, 256>>>(N);

    // layer 2 (+fused epilogue)
    k_gemm2<<<(N + 63) / 64, 256>>>(W2, b1, N);
    k_gather2<<<(N + 7) / 8, 256>>>(out, b2, N);
}